// round 13
// baseline (speedup 1.0000x reference)
#include <cuda_runtime.h>
#include <cuda_fp16.h>
#include <cstdint>
#include <cstddef>

#define F_IN  128
#define F_HID 64
#define F_OUT 40
#define MAXN  100032
#define MAXE  1600000
#define SCAN_B 512
#define MAXNB  256   // max scan blocks (N <= 131072)

// ---------------- scratch (no allocation allowed) ----------------
__device__ __align__(256) __half g_h1h[(size_t)MAXN * F_HID];  // fp16: dis[r]*(x@W1^T)[r]
__device__ __align__(256) float  g_agg1[(size_t)MAXN * F_HID]; // fp32 layer-1 aggregate
__device__ __align__(256) __half g_h3h[(size_t)MAXN * F_OUT];  // fp16: dis[r]*(relu@W2^T)[r]
__device__ float g_dis[MAXN];
__device__ int   g_cnt[MAXN];       // zero-init at load; re-zeroed by agg2 for next replay
__device__ int   g_rowptr[MAXN + 1];
__device__ int   g_cursor[MAXN];
__device__ int   g_blocksum[MAXNB];
__device__ int   g_perm[MAXE];

// ---------------- bit-cast helpers ----------------
__device__ __forceinline__ unsigned h2_as_u32(__half2 h) {
    return *reinterpret_cast<unsigned*>(&h);
}
__device__ __forceinline__ __half2 u32_as_h2(unsigned u) {
    return *reinterpret_cast<__half2*>(&u);
}

// ---------------- packed f32x2 helpers ----------------
__device__ __forceinline__ void ffma2(unsigned long long& d, unsigned long long a,
                                      unsigned long long b) {
    asm("fma.rn.f32x2 %0, %1, %2, %0;" : "+l"(d) : "l"(a), "l"(b));
}
__device__ __forceinline__ void unpack2(unsigned long long v, float& x, float& y) {
    asm("mov.b64 {%0, %1}, %2;" : "=f"(x), "=f"(y) : "l"(v));
}

// ---------------- K1: in-degree count (edge_index is int32 on this dataset) ----
__global__ void k_count(const int* __restrict__ ei, int E, int N) {
    int e = blockIdx.x * blockDim.x + threadIdx.x;
    if (e < E) {
        int c = ei[(size_t)E + e];
        if ((unsigned)c < (unsigned)N) atomicAdd(&g_cnt[c], 1);
    }
}

// ---------------- K2: block scan of cnt (+dis) ----------------
__global__ __launch_bounds__(SCAN_B) void k_scan1(int N) {
    __shared__ int s[SCAN_B];
    int t = threadIdx.x;
    int i = blockIdx.x * SCAN_B + t;
    int val = (i < N) ? g_cnt[i] : 0;
    s[t] = val;
    __syncthreads();
#pragma unroll
    for (int off = 1; off < SCAN_B; off <<= 1) {
        int x = (t >= off) ? s[t - off] : 0;
        __syncthreads();
        s[t] += x;
        __syncthreads();
    }
    if (i < N) {
        g_rowptr[i] = s[t] - val;          // exclusive within block
        float d = (float)val;
        g_dis[i] = (d > 0.f) ? rsqrtf(d) : 0.f;
    }
    if (t == SCAN_B - 1) g_blocksum[blockIdx.x] = s[t];
}

// ---------------- K3: finish scan (each block redundantly scans blocksums) ----
__global__ __launch_bounds__(256) void k_scan23(int N, int nb) {
    __shared__ int s[MAXNB];
    __shared__ int sx[MAXNB + 1];
    int t = threadIdx.x;
    int val = (t < nb) ? g_blocksum[t] : 0;
    s[t] = val;
    __syncthreads();
#pragma unroll
    for (int off = 1; off < MAXNB; off <<= 1) {
        int x = (t >= off) ? s[t - off] : 0;
        __syncthreads();
        s[t] += x;
        __syncthreads();
    }
    sx[t] = s[t] - val;
    if (t == MAXNB - 1) sx[MAXNB] = s[t];
    __syncthreads();

    int i = blockIdx.x * 256 + t;
    if (i < N) {
        int v = g_rowptr[i] + sx[i / SCAN_B];
        g_rowptr[i] = v;
        g_cursor[i] = v;
    }
    if (blockIdx.x == 0 && t == 0) g_rowptr[N] = sx[MAXNB];
}

// ---------------- K4: CSR fill ----------------
__global__ void k_fill(const int* __restrict__ ei, int E, int N) {
    int e = blockIdx.x * blockDim.x + threadIdx.x;
    if (e < E) {
        int r = ei[e];
        int c = ei[(size_t)E + e];
        if ((unsigned)r < (unsigned)N && (unsigned)c < (unsigned)N) {
            int pos = atomicAdd(&g_cursor[c], 1);
            if ((unsigned)pos < (unsigned)MAXE) g_perm[pos] = r;
        }
    }
}

// ---------------- K5: GEMM1  h1h = fp16( dis .* (x @ W1^T) ) ----------------
// 256 thr, 128 rows x 64 cols. Thread: 4 row-pairs x 4 cols, FFMA2 core.
__global__ __launch_bounds__(256) void gemm1_kernel(const float* __restrict__ x,
                                                    const float* __restrict__ W1, int N) {
    __shared__ float2 xs2[32][65];   // [kk][rowpair]
    __shared__ float2 wd[32][65];    // [kk][j] duplicated (w,w)

    int tid = threadIdx.x;
    int tx = tid & 15;
    int ty = tid >> 4;
    int rbase = blockIdx.x * 128;

    unsigned long long acc[4][4];
#pragma unroll
    for (int r = 0; r < 4; r++)
#pragma unroll
        for (int c = 0; c < 4; c++) acc[r][c] = 0ull;

#pragma unroll 1
    for (int kp = 0; kp < 4; kp++) {
        __syncthreads();
#pragma unroll
        for (int it = 0; it < 16; it++) {
            int idx = it * 256 + tid;
            int rr = idx >> 5, kk = idx & 31;
            int gr = rbase + rr;
            float v = (gr < N) ? x[(size_t)gr * F_IN + kp * 32 + kk] : 0.f;
            ((float*)&xs2[kk][rr >> 1])[rr & 1] = v;
        }
#pragma unroll
        for (int it = 0; it < 8; it++) {
            int idx = it * 256 + tid;
            int j = idx >> 5, kk = idx & 31;
            float v = W1[j * F_IN + kp * 32 + kk];
            wd[kk][j] = make_float2(v, v);
        }
        __syncthreads();

#pragma unroll
        for (int kk = 0; kk < 32; kk++) {
            unsigned long long xp[4], wv[4];
#pragma unroll
            for (int r = 0; r < 4; r++)
                xp[r] = *(const unsigned long long*)&xs2[kk][4 * ty + r];
#pragma unroll
            for (int c = 0; c < 4; c++)
                wv[c] = *(const unsigned long long*)&wd[kk][4 * tx + c];
#pragma unroll
            for (int r = 0; r < 4; r++)
#pragma unroll
                for (int c = 0; c < 4; c++) ffma2(acc[r][c], xp[r], wv[c]);
        }
    }

#pragma unroll
    for (int r = 0; r < 4; r++) {
        int row0 = rbase + 2 * (4 * ty + r);
        if (row0 >= N) break;
        float d0 = g_dis[row0];
        float d1 = (row0 + 1 < N) ? g_dis[row0 + 1] : 0.f;
        float lo[4], hi[4];
#pragma unroll
        for (int c = 0; c < 4; c++) unpack2(acc[r][c], lo[c], hi[c]);
        {
            __half2 p0 = __floats2half2_rn(lo[0] * d0, lo[1] * d0);
            __half2 p1 = __floats2half2_rn(lo[2] * d0, lo[3] * d0);
            *(uint2*)&g_h1h[(size_t)row0 * F_HID + 4 * tx] =
                make_uint2(h2_as_u32(p0), h2_as_u32(p1));
        }
        if (row0 + 1 < N) {
            __half2 p0 = __floats2half2_rn(hi[0] * d1, hi[1] * d1);
            __half2 p1 = __floats2half2_rn(hi[2] * d1, hi[3] * d1);
            *(uint2*)&g_h1h[(size_t)(row0 + 1) * F_HID + 4 * tx] =
                make_uint2(h2_as_u32(p0), h2_as_u32(p1));
        }
    }
}

// ---------------- K6: aggregation layer 1 (fp16 gather, fp32 accum) ----------
// warp per node; 4 edge groups x 8 chunks; each lane loads uint4 = 8 halves.
__global__ __launch_bounds__(256) void agg1_kernel(int N) {
    int wid = threadIdx.x >> 5;
    int lane = threadIdx.x & 31;
    int node = blockIdx.x * 8 + wid;
    if (node >= N) return;

    int start = g_rowptr[node];
    int end   = g_rowptr[node + 1];
    int eg = lane >> 3;        // edge group 0-3
    int ch = lane & 7;         // uint4 chunk 0-7 (row = 8 x uint4)

    const uint4* h = (const uint4*)g_h1h;
    float acc[8];
#pragma unroll
    for (int i = 0; i < 8; i++) acc[i] = 0.f;

#pragma unroll 2
    for (int k = start + eg; k < end; k += 4) {
        int r = g_perm[k];
        uint4 v = __ldg(&h[(size_t)r * 8 + ch]);
        float2 f0 = __half22float2(u32_as_h2(v.x));
        float2 f1 = __half22float2(u32_as_h2(v.y));
        float2 f2 = __half22float2(u32_as_h2(v.z));
        float2 f3 = __half22float2(u32_as_h2(v.w));
        acc[0] += f0.x; acc[1] += f0.y; acc[2] += f1.x; acc[3] += f1.y;
        acc[4] += f2.x; acc[5] += f2.y; acc[6] += f3.x; acc[7] += f3.y;
    }
    // tree-reduce 4 edge groups (stride-8 aligned): down16 then down8
#pragma unroll
    for (int i = 0; i < 8; i++) acc[i] += __shfl_down_sync(0xffffffffu, acc[i], 16);
#pragma unroll
    for (int i = 0; i < 8; i++) acc[i] += __shfl_down_sync(0xffffffffu, acc[i], 8);

    if (lane < 8) {
        float di = g_dis[node];
        float4* o = (float4*)&g_agg1[(size_t)node * F_HID + 8 * ch];
        o[0] = make_float4(acc[0] * di, acc[1] * di, acc[2] * di, acc[3] * di);
        o[1] = make_float4(acc[4] * di, acc[5] * di, acc[6] * di, acc[7] * di);
    }
}

// ---------------- K7: GEMM2  h3h = fp16( dis .* (relu(agg1+b1) @ W2^T) ) ------
// 320 thr: tx=tid%10 -> cols 4tx..4tx+3; ty=tid/10 (0..31) -> rowpairs 2ty,2ty+1.
__global__ __launch_bounds__(320) void gemm2_kernel(const float* __restrict__ W2,
                                                    const float* __restrict__ b1, int N) {
    __shared__ float2 xs2[32][65];
    __shared__ float2 wd[32][41];

    int tid = threadIdx.x;
    int tx = tid % 10;
    int ty = tid / 10;
    int rbase = blockIdx.x * 128;

    unsigned long long acc[2][4];
#pragma unroll
    for (int r = 0; r < 2; r++)
#pragma unroll
        for (int c = 0; c < 4; c++) acc[r][c] = 0ull;

#pragma unroll 1
    for (int kp = 0; kp < 2; kp++) {
        __syncthreads();
        for (int idx = tid; idx < 128 * 32; idx += 320) {
            int rr = idx >> 5, kk = idx & 31;
            int gr = rbase + rr;
            float v = 0.f;
            if (gr < N)
                v = fmaxf(g_agg1[(size_t)gr * F_HID + kp * 32 + kk] + b1[kp * 32 + kk], 0.f);
            ((float*)&xs2[kk][rr >> 1])[rr & 1] = v;
        }
        for (int idx = tid; idx < F_OUT * 32; idx += 320) {
            int j = idx >> 5, kk = idx & 31;
            float v = W2[j * F_HID + kp * 32 + kk];
            wd[kk][j] = make_float2(v, v);
        }
        __syncthreads();

#pragma unroll
        for (int kk = 0; kk < 32; kk++) {
            unsigned long long xp[2], wv[4];
#pragma unroll
            for (int r = 0; r < 2; r++)
                xp[r] = *(const unsigned long long*)&xs2[kk][2 * ty + r];
#pragma unroll
            for (int c = 0; c < 4; c++)
                wv[c] = *(const unsigned long long*)&wd[kk][4 * tx + c];
#pragma unroll
            for (int r = 0; r < 2; r++)
#pragma unroll
                for (int c = 0; c < 4; c++) ffma2(acc[r][c], xp[r], wv[c]);
        }
    }

#pragma unroll
    for (int r = 0; r < 2; r++) {
        int row0 = rbase + 2 * (2 * ty + r);
        if (row0 >= N) break;
        float d0 = g_dis[row0];
        float d1 = (row0 + 1 < N) ? g_dis[row0 + 1] : 0.f;
        float lo[4], hi[4];
#pragma unroll
        for (int c = 0; c < 4; c++) unpack2(acc[r][c], lo[c], hi[c]);
        {
            __half2 p0 = __floats2half2_rn(lo[0] * d0, lo[1] * d0);
            __half2 p1 = __floats2half2_rn(lo[2] * d0, lo[3] * d0);
            *(uint2*)&g_h3h[(size_t)row0 * F_OUT + 4 * tx] =
                make_uint2(h2_as_u32(p0), h2_as_u32(p1));
        }
        if (row0 + 1 < N) {
            __half2 p0 = __floats2half2_rn(hi[0] * d1, hi[1] * d1);
            __half2 p1 = __floats2half2_rn(hi[2] * d1, hi[3] * d1);
            *(uint2*)&g_h3h[(size_t)(row0 + 1) * F_OUT + 4 * tx] =
                make_uint2(h2_as_u32(p0), h2_as_u32(p1));
        }
    }
}

// ---------------- K8: aggregation layer 2 + b2 -> out ------------------------
// warp per node; 6 edge groups x 5 chunks (30 lanes); uint4 = 8 halves per lane.
// Also re-zeros g_cnt for the next graph replay (cnt consumed by k_scan1 only).
__global__ __launch_bounds__(256) void agg2_kernel(float* __restrict__ out,
                                                   const float* __restrict__ b2, int N) {
    int gi = blockIdx.x * 256 + threadIdx.x;
    if (gi < N) g_cnt[gi] = 0;           // prep next replay (zero-init covers call 1)

    int wid = threadIdx.x >> 5;
    int lane = threadIdx.x & 31;
    int node = blockIdx.x * 8 + wid;
    if (node >= N) return;

    int start = g_rowptr[node];
    int end   = g_rowptr[node + 1];
    int eg = lane / 5;         // edge group 0-5 (lanes 30,31 idle -> eg 6)
    int ch = lane - eg * 5;    // uint4 chunk 0-4 (row = 5 x uint4)

    const uint4* h = (const uint4*)g_h3h;
    float acc[8];
#pragma unroll
    for (int i = 0; i < 8; i++) acc[i] = 0.f;

    if (eg < 6) {
#pragma unroll 2
        for (int k = start + eg; k < end; k += 6) {
            int r = g_perm[k];
            uint4 v = __ldg(&h[(size_t)r * 5 + ch]);
            float2 f0 = __half22float2(u32_as_h2(v.x));
            float2 f1 = __half22float2(u32_as_h2(v.y));
            float2 f2 = __half22float2(u32_as_h2(v.z));
            float2 f3 = __half22float2(u32_as_h2(v.w));
            acc[0] += f0.x; acc[1] += f0.y; acc[2] += f1.x; acc[3] += f1.y;
            acc[4] += f2.x; acc[5] += f2.y; acc[6] += f3.x; acc[7] += f3.y;
        }
    }
    // combine 6 groups at strides 5,10,15,20,25 (temps read pre-update values)
#pragma unroll
    for (int i = 0; i < 8; i++) {
        float t1 = __shfl_down_sync(0xffffffffu, acc[i], 5);
        float t2 = __shfl_down_sync(0xffffffffu, acc[i], 10);
        float t3 = __shfl_down_sync(0xffffffffu, acc[i], 15);
        float t4 = __shfl_down_sync(0xffffffffu, acc[i], 20);
        float t5 = __shfl_down_sync(0xffffffffu, acc[i], 25);
        acc[i] += (t1 + t2) + (t3 + t4) + t5;
    }

    if (lane < 5) {
        float di = g_dis[node];
        const float4* bb = (const float4*)b2;     // 10 float4
        float4 b0 = __ldg(&bb[2 * lane]);
        float4 b1v = __ldg(&bb[2 * lane + 1]);
        float4* o = (float4*)&out[(size_t)node * F_OUT + 8 * lane];
        o[0] = make_float4(fmaf(acc[0], di, b0.x), fmaf(acc[1], di, b0.y),
                           fmaf(acc[2], di, b0.z), fmaf(acc[3], di, b0.w));
        o[1] = make_float4(fmaf(acc[4], di, b1v.x), fmaf(acc[5], di, b1v.y),
                           fmaf(acc[6], di, b1v.z), fmaf(acc[7], di, b1v.w));
    }
}

// ---------------- launch ----------------
extern "C" void kernel_launch(void* const* d_in, const int* in_sizes, int n_in,
                              void* d_out, int out_size) {
    const float* x = nullptr; const int* ei = nullptr;
    const float* W1 = nullptr; const float* b1 = nullptr;
    const float* W2 = nullptr; const float* b2 = nullptr;
    int x_sz = 0, ei_sz = 0;

    for (int i = 0; i < n_in; i++) {
        int s = in_sizes[i];
        if (s == 8192)       W1 = (const float*)d_in[i];
        else if (s == 2560)  W2 = (const float*)d_in[i];
        else if (s == 64)    b1 = (const float*)d_in[i];
        else if (s == 40)    b2 = (const float*)d_in[i];
        else if (s == 12800000) { x = (const float*)d_in[i]; x_sz = s; }
        else if (s == 3200000)  { ei = (const int*)d_in[i]; ei_sz = s; }
    }
    if (!x || !ei || !W1 || !b1 || !W2 || !b2) {
        x  = (const float*)d_in[0];  x_sz  = in_sizes[0];
        ei = (const int*)d_in[1];    ei_sz = in_sizes[1];
        W1 = (const float*)d_in[2];
        b1 = (const float*)d_in[3];
        W2 = (const float*)d_in[4];
        b2 = (const float*)d_in[5];
    }

    float* out = (float*)d_out;
    int N = x_sz / F_IN;
    int E = ei_sz / 2;
    if (N > MAXN) N = MAXN;
    if (E > MAXE) E = MAXE;
    int nb = (N + SCAN_B - 1) / SCAN_B;

    k_count <<<(E + 255) / 256, 256>>>(ei, E, N);
    k_scan1 <<<nb, SCAN_B>>>(N);
    k_scan23<<<(N + 255) / 256, 256>>>(N, nb);
    k_fill  <<<(E + 255) / 256, 256>>>(ei, E, N);

    gemm1_kernel<<<(N + 127) / 128, 256>>>(x, W1, N);
    agg1_kernel <<<(N + 7) / 8, 256>>>(N);
    gemm2_kernel<<<(N + 127) / 128, 320>>>(W2, b1, N);
    agg2_kernel <<<(N + 7) / 8, 256>>>(out, b2, N);
}